// round 8
// baseline (speedup 1.0000x reference)
#include <cuda_runtime.h>
#include <cuda_bf16.h>
#include <cstdint>

// Problem constants
#define B_   128
#define L_   512
#define W_   256
#define CN_  4
#define G_   4
#define Lp_  508            // L - KH + 1
#define NB_  65024          // B_*Lp_ = 508*128 exactly
#define LBL_ 53
#define EPSF 1e-5f
#define NEGF (-100000.0f)
#define FNEG (-3.0e38f)

#define HROW 68             // b32 per l row of h (136 bf16: 130 data + 6 pad)
#define K1PW 352            // b32 k-pairs per conv1 weight row (704 bf16)
#define C1_NIT 22           // 352/16
#define NCH 8               // l-chunks for partial max

// Scratch (static device memory -- no allocations allowed)
__device__ uint32_t g_hb[(size_t)B_ * L_ * HROW + 4096]; // bf16-pair h, [b*L+l][68]
__device__ uint32_t g_w1h[(size_t)W_ * K1PW];            // conv1 w [w][352]
__device__ uint32_t g_cbwh[(size_t)CN_ * W_ * 128];      // cb w, bf16 [i][256][128 b32]
__device__ uint32_t g_yh[(size_t)NB_ * 128];             // y bf16 pairs [nb][128 b32]
__device__ float    g_y[(size_t)NB_ * W_];               // [nb][w]
__device__ float    g_z[(size_t)NB_ * W_];
__device__ float    g_xI[(size_t)NB_ * W_];
__device__ float    g_psum[B_ * G_ * 2];                 // (sum, sumsq) accum
__device__ float2   g_stats[B_ * G_];                    // (mean, rstd)
__device__ float    g_pmax[B_ * NCH * 3 * W_];
__device__ float    g_feat[B_ * 3 * W_];

// ---------------------------------------------------------------------------
// helpers
// ---------------------------------------------------------------------------
__device__ __forceinline__ uint32_t cvta_s(const void* p) {
    return (uint32_t)__cvta_generic_to_shared(p);
}
__device__ __forceinline__ void cp16(uint32_t s, const void* g) {
    asm volatile("cp.async.cg.shared.global [%0],[%1],16;" :: "r"(s), "l"(g));
}
#define CP_COMMIT() asm volatile("cp.async.commit_group;")
#define CP_WAIT2()  asm volatile("cp.async.wait_group 2;")
#define CP_WAIT1()  asm volatile("cp.async.wait_group 1;")
#define CP_WAIT0()  asm volatile("cp.async.wait_group 0;")

__device__ __forceinline__ void ldm4(uint32_t* r, uint32_t addr) {
    asm volatile("ldmatrix.sync.aligned.m8n8.x4.shared.b16 {%0,%1,%2,%3}, [%4];"
        : "=r"(r[0]), "=r"(r[1]), "=r"(r[2]), "=r"(r[3]) : "r"(addr));
}

__device__ __forceinline__ void mma16(float* c, const uint32_t* a,
                                      uint32_t b0, uint32_t b1) {
    asm volatile(
        "mma.sync.aligned.m16n8k16.row.col.f32.bf16.bf16.f32 "
        "{%0,%1,%2,%3}, {%4,%5,%6,%7}, {%8,%9}, {%0,%1,%2,%3};"
        : "+f"(c[0]), "+f"(c[1]), "+f"(c[2]), "+f"(c[3])
        : "r"(a[0]), "r"(a[1]), "r"(a[2]), "r"(a[3]), "r"(b0), "r"(b1));
}

__device__ __forceinline__ uint32_t packbf(float lo, float hi) {
    __nv_bfloat162 t = __floats2bfloat162_rn(lo, hi);
    return *(uint32_t*)&t;
}

// ---------------------------------------------------------------------------
// 0a) conv1 weight prep: [w][650] fp32 -> [w][352] bf16-pair (window layout)
// ---------------------------------------------------------------------------
__global__ void prep_w1h(const float* __restrict__ w)
{
    int idx = blockIdx.x * 256 + threadIdx.x;
    if (idx >= W_ * K1PW) return;
    int m = idx / K1PW, kp = idx - m * K1PW;
    int ks = 2 * kp;
    float v0 = 0.f, v1 = 0.f;
    int seg0 = ks / 136, off0 = ks - seg0 * 136;
    if (seg0 < 5 && off0 < 130)     v0 = w[m * 650 + seg0 * 130 + off0];
    int ks1 = ks + 1;
    int seg1 = ks1 / 136, off1 = ks1 - seg1 * 136;
    if (seg1 < 5 && off1 < 130)     v1 = w[m * 650 + seg1 * 130 + off1];
    g_w1h[idx] = packbf(v0, v1);
}

// ---------------------------------------------------------------------------
// 0b) cb weight prep + psum zero init
// ---------------------------------------------------------------------------
__global__ void prep_cbwh(const float* __restrict__ w)
{
    int idx = blockIdx.x * 256 + threadIdx.x;
    if (idx < B_ * G_ * 2) g_psum[idx] = 0.f;
    if (idx >= CN_ * W_ * 128) return;
    int row = idx >> 7;
    int kp  = idx & 127;
    const float* src = w + (size_t)row * W_ + 2 * kp;
    g_cbwh[idx] = packbf(src[0], src[1]);
}

// ---------------------------------------------------------------------------
// 1) embedding + position -> g_hb bf16 pairs [b*L+l][68]; zeros pad + tail
// ---------------------------------------------------------------------------
__global__ void embed_h(const int* __restrict__ x,
                        const float* __restrict__ pe,
                        const float* __restrict__ emb)
{
    int id = blockIdx.x * 256 + threadIdx.x;
    const int MAIN = B_ * L_ * HROW;
    if (id >= MAIN + 4096) return;
    if (id >= MAIN) { g_hb[id] = 0u; return; }
    int bl = id / HROW, t = id - bl * HROW;
    float v0 = 0.f, v1 = 0.f;
    if (t < 64) {
        int tok = x[bl];
        const float* e = emb + (size_t)tok * 128 + 2 * t;
        v0 = e[0]; v1 = e[1];
    } else if (t == 64) {
        v0 = pe[bl * 2]; v1 = pe[bl * 2 + 1];
    }
    g_hb[id] = packbf(v0, v1);
}

// ---------------------------------------------------------------------------
// 2) conv1: C[n][w] = window(h)[n][704] @ w1[w][704]^T, per-batch.
// ---------------------------------------------------------------------------
__global__ __launch_bounds__(256, 2) void conv1_tc(
    const float* __restrict__ bias,
    const float* __restrict__ bg, const float* __restrict__ bb,
    const float* __restrict__ bmu, const float* __restrict__ bvv,
    const float* __restrict__ pw)
{
    extern __shared__ uint32_t sm[];
    uint32_t sb = cvta_s(sm);
    int b  = blockIdx.z;
    int m0 = blockIdx.y * 128;     // n-position tile
    int n0 = blockIdx.x * 128;     // w tile
    int t = threadIdx.x, lane = t & 31, wid = t >> 5;
    int wm = wid >> 2, wn = wid & 3;
    int fr = lane >> 2, fc = lane & 3;

    float acc[4][4][4];
    #pragma unroll
    for (int i = 0; i < 4; i++)
        #pragma unroll
        for (int j = 0; j < 4; j++)
            #pragma unroll
            for (int q = 0; q < 4; q++) acc[i][j][q] = 0.f;

    int lr = t >> 1, lc = (t & 1) * 8;
    const uint32_t* agp = g_hb + (size_t)(b * 512 + m0 + lr) * HROW + lc;
    const uint32_t* wgp = g_w1h + (size_t)(n0 + lr) * K1PW + lc;
    uint32_t aS = sb + lr * 80 + lc * 4;
    uint32_t wS = sb + 30720 + lr * 80 + lc * 4;

    uint32_t aAddr[4];
    #pragma unroll
    for (int i = 0; i < 4; i++) {
        int row = wm * 64 + 16 * i + (lane & 15);
        int col = (lane & 16) ? 4 : 0;
        aAddr[i] = sb + row * 80 + col * 4;
    }
    uint32_t bAddr = sb + 30720 + (wn * 32 + lane) * 80;

    #define C1_ISSUE(it_) do { \
        uint32_t so_ = ((it_) % 3) * 10240; \
        cp16(aS + so_, agp + (it_) * 16); \
        cp16(aS + so_ + 16, agp + (it_) * 16 + 4); \
        cp16(wS + so_, wgp + (it_) * 16); \
        cp16(wS + so_ + 16, wgp + (it_) * 16 + 4); \
    } while (0)

    C1_ISSUE(0); CP_COMMIT();
    C1_ISSUE(1); CP_COMMIT();

    for (int it = 0; it < C1_NIT; it++) {
        if (it < C1_NIT - 1) CP_WAIT1(); else CP_WAIT0();
        __syncthreads();
        uint32_t so = (it % 3) * 10240;
        #pragma unroll
        for (int ss = 0; ss < 2; ss++) {
            uint32_t ko = so + ss * 32;
            uint32_t af[4][4], b0q[4], b1q[4];
            #pragma unroll
            for (int i = 0; i < 4; i++) ldm4(af[i], aAddr[i] + ko);
            ldm4(b0q, bAddr + ko);
            ldm4(b1q, bAddr + ko + 16);
            #pragma unroll
            for (int i = 0; i < 4; i++)
                #pragma unroll
                for (int j = 0; j < 4; j++)
                    mma16(acc[i][j], af[i], b0q[j], b1q[j]);
        }
        if (it + 2 < C1_NIT) { C1_ISSUE(it + 2); CP_COMMIT(); }
    }

    float p = pw[0];
    #pragma unroll
    for (int j = 0; j < 4; j++) {
        int c = n0 + wn * 32 + 8 * j + 2 * fc;
        float s0 = rsqrtf(bvv[c] + EPSF) * bg[c];
        float o0 = bb[c] - bmu[c] * s0 + bias[c] * s0;
        float s1 = rsqrtf(bvv[c + 1] + EPSF) * bg[c + 1];
        float o1 = bb[c + 1] - bmu[c + 1] * s1 + bias[c + 1] * s1;
        #pragma unroll
        for (int i = 0; i < 4; i++) {
            int r0 = m0 + wm * 64 + 16 * i + fr;
            int r1 = r0 + 8;
            if (r0 < Lp_) {
                size_t nb = (size_t)b * Lp_ + r0;
                float v0 = acc[i][j][0] * s0 + o0;
                float v1 = acc[i][j][1] * s1 + o1;
                v0 = v0 > 0.f ? v0 : p * v0;
                v1 = v1 > 0.f ? v1 : p * v1;
                *(float2*)(g_xI + nb * W_ + c) = make_float2(v0, v1);
                g_yh[nb * 128 + (c >> 1)] = packbf(v0, v1);
            }
            if (r1 < Lp_) {
                size_t nb = (size_t)b * Lp_ + r1;
                float v2 = acc[i][j][2] * s0 + o0;
                float v3 = acc[i][j][3] * s1 + o1;
                v2 = v2 > 0.f ? v2 : p * v2;
                v3 = v3 > 0.f ? v3 : p * v3;
                *(float2*)(g_xI + nb * W_ + c) = make_float2(v2, v3);
                g_yh[nb * 128 + (c >> 1)] = packbf(v2, v3);
            }
        }
    }
}

// ---------------------------------------------------------------------------
// 3) cb GEMM v2: weight-resident multi-tile.
//    CTA = 128-col weight slice (resident, full K=256) x 4 consecutive
//    128-row tiles streamed through a 4-stage cp.async A ring.
//    64 continuous k16 steps; epilogue (bias + z + fused GN stats) per tile.
//    smem: A ring 4*6144 + W 128*528 = 92160 B.
// ---------------------------------------------------------------------------
__global__ __launch_bounds__(256, 2) void cb_tc2(int blk, const float* __restrict__ bias)
{
    extern __shared__ uint32_t sm4[];
    __shared__ float sred[8];
    uint32_t sb = cvta_s(sm4);
    const uint32_t A0 = sb;                 // 4 stages * 6144 B
    const uint32_t W0 = sb + 24576;         // 128 rows * 528 B
    int n0 = blockIdx.x * 128;
    int tgrp = blockIdx.y;                  // 0..126, tiles tgrp*4 .. +3
    int t = threadIdx.x, lane = t & 31, wid = t >> 5;
    int wm = wid >> 2, wn = wid & 3;
    int fr = lane >> 2, fc = lane & 3;
    if (t < 8) sred[t] = 0.f;

    // resident weight load (bundled into cp.async group 0)
    {
        const char* wbase = (const char*)g_cbwh + (size_t)(blk * 256 + n0) * 512;
        #pragma unroll
        for (int i = 0; i < 16; i++) {
            int c = t + 256 * i;
            int row = c >> 5, col = c & 31;
            cp16(W0 + row * 528 + col * 16, wbase + row * 512 + col * 16);
        }
    }

    int arow = t >> 1, ahalf = t & 1;
    const char* abase = (const char*)g_yh +
        ((size_t)(tgrp * 4) * 128 + arow) * 512 + ahalf * 16;
    uint32_t aS = A0 + arow * 48 + ahalf * 16;

    #define CB2_ISSUE(s_) \
        cp16(aS + ((s_) & 3) * 6144, \
             abase + (size_t)((s_) >> 4) * 65536 + ((s_) & 15) * 32)

    CB2_ISSUE(0); CP_COMMIT();
    CB2_ISSUE(1); CP_COMMIT();
    CB2_ISSUE(2); CP_COMMIT();

    uint32_t aAddr[4];
    #pragma unroll
    for (int i = 0; i < 4; i++)
        aAddr[i] = A0 + (wm * 64 + 16 * i + (lane & 15)) * 48 + ((lane & 16) ? 16 : 0);
    uint32_t bAddr = W0 + (wn * 32 + lane) * 528;

    float acc[4][4][4];

    for (int s = 0; s < 64; s++) {
        if ((s & 15) == 0) {
            #pragma unroll
            for (int i = 0; i < 4; i++)
                #pragma unroll
                for (int j = 0; j < 4; j++)
                    #pragma unroll
                    for (int q = 0; q < 4; q++) acc[i][j][q] = 0.f;
        }
        if (s < 62) CP_WAIT2(); else if (s == 62) CP_WAIT1(); else CP_WAIT0();
        __syncthreads();
        {
            uint32_t so = (s & 3) * 6144;
            uint32_t ko = (s & 15) * 32;
            uint32_t af[4][4], b0q[4], b1q[4];
            #pragma unroll
            for (int i = 0; i < 4; i++) ldm4(af[i], aAddr[i] + so);
            ldm4(b0q, bAddr + ko);
            ldm4(b1q, bAddr + ko + 16);
            #pragma unroll
            for (int i = 0; i < 4; i++)
                #pragma unroll
                for (int j = 0; j < 4; j++)
                    mma16(acc[i][j], af[i], b0q[j], b1q[j]);
        }
        if (s + 3 < 64) { CB2_ISSUE(s + 3); CP_COMMIT(); }

        if ((s & 15) == 15) {
            // epilogue for tile (s >> 4)
            int tile = tgrp * 4 + (s >> 4);
            int m0 = tile * 128;
            float rs[4][2], rq[4][2];
            #pragma unroll
            for (int i = 0; i < 4; i++) { rs[i][0] = rs[i][1] = rq[i][0] = rq[i][1] = 0.f; }
            #pragma unroll
            for (int j = 0; j < 4; j++) {
                int c = n0 + wn * 32 + 8 * j + 2 * fc;
                float bi0 = bias[c], bi1 = bias[c + 1];
                #pragma unroll
                for (int i = 0; i < 4; i++) {
                    size_t r0 = m0 + wm * 64 + 16 * i + fr;
                    size_t r1 = r0 + 8;
                    float v0 = acc[i][j][0] + bi0, v1 = acc[i][j][1] + bi1;
                    float v2 = acc[i][j][2] + bi0, v3 = acc[i][j][3] + bi1;
                    *(float2*)(g_z + r0 * W_ + c) = make_float2(v0, v1);
                    *(float2*)(g_z + r1 * W_ + c) = make_float2(v2, v3);
                    rs[i][0] += v0 + v1; rq[i][0] += v0 * v0 + v1 * v1;
                    rs[i][1] += v2 + v3; rq[i][1] += v2 * v2 + v3 * v3;
                }
            }
            int b0v = m0 / Lp_;
            int thr = (b0v + 1) * Lp_;
            float s0 = 0.f, q0 = 0.f, s1 = 0.f, q1 = 0.f;
            #pragma unroll
            for (int i = 0; i < 4; i++) {
                int r0 = m0 + wm * 64 + 16 * i + fr;
                if (r0 >= thr) { s1 += rs[i][0]; q1 += rq[i][0]; }
                else           { s0 += rs[i][0]; q0 += rq[i][0]; }
                if (r0 + 8 >= thr) { s1 += rs[i][1]; q1 += rq[i][1]; }
                else               { s0 += rs[i][1]; q0 += rq[i][1]; }
            }
            #pragma unroll
            for (int o = 16; o > 0; o >>= 1) {
                s0 += __shfl_xor_sync(0xffffffffu, s0, o);
                q0 += __shfl_xor_sync(0xffffffffu, q0, o);
                s1 += __shfl_xor_sync(0xffffffffu, s1, o);
                q1 += __shfl_xor_sync(0xffffffffu, q1, o);
            }
            int gslot = wn >> 1;
            if (lane == 0) {
                atomicAdd(&sred[gslot * 2 + 0], s0);
                atomicAdd(&sred[gslot * 2 + 1], q0);
                atomicAdd(&sred[4 + gslot * 2 + 0], s1);
                atomicAdd(&sred[4 + gslot * 2 + 1], q1);
            }
            __syncthreads();
            if (t < 8) {
                int bslot = t >> 2, gs = (t >> 1) & 1, sq = t & 1;
                int bb = b0v + bslot;
                if (bb < B_) {
                    int g = (n0 >> 6) + gs;
                    atomicAdd(&g_psum[(bb * G_ + g) * 2 + sq], sred[t]);
                }
                sred[t] = 0.f;
            }
            __syncthreads();
        }
    }
}

// ---------------------------------------------------------------------------
// 4) stats finalize: psum -> g_stats; re-zero psum for next iteration
// ---------------------------------------------------------------------------
__global__ void stats_fin()
{
    int t = blockIdx.x * 256 + threadIdx.x;
    if (t >= B_ * G_) return;
    float s = g_psum[t * 2], q = g_psum[t * 2 + 1];
    float cnt = (float)(64 * Lp_);
    float mean = s / cnt;
    float var  = q / cnt - mean * mean;
    g_stats[t] = make_float2(mean, rsqrtf(var + EPSF));
    g_psum[t * 2] = 0.f;
    g_psum[t * 2 + 1] = 0.f;
}

// ---------------------------------------------------------------------------
// 5) GroupNorm apply + PReLU + residual
// ---------------------------------------------------------------------------
__global__ void gnapply_kernel(const float* __restrict__ yprev,
                               const float* __restrict__ gamma,
                               const float* __restrict__ beta,
                               const float* __restrict__ pp)
{
    unsigned i4 = blockIdx.x * 256u + threadIdx.x;
    if (i4 >= (unsigned)NB_ * 64u) return;
    unsigned nb = i4 >> 6, wq = i4 & 63;
    unsigned w0 = wq * 4;
    unsigned b = nb / Lp_;
    float2 st = g_stats[b * G_ + (wq >> 4)];
    float ga0 = gamma[w0] * st.y,     be0 = beta[w0] - st.x * ga0;
    float ga1 = gamma[w0 + 1] * st.y, be1 = beta[w0 + 1] - st.x * ga1;
    float ga2 = gamma[w0 + 2] * st.y, be2 = beta[w0 + 2] - st.x * ga2;
    float ga3 = gamma[w0 + 3] * st.y, be3 = beta[w0 + 3] - st.x * ga3;
    float p = pp[0];
    size_t o = (size_t)nb * W_ + w0;
    float4 z = *(const float4*)(g_z + o);
    float4 y = *(const float4*)(yprev + o);
    float v;
    v = z.x * ga0 + be0; y.x += (v > 0.f ? v : p * v);
    v = z.y * ga1 + be1; y.y += (v > 0.f ? v : p * v);
    v = z.z * ga2 + be2; y.z += (v > 0.f ? v : p * v);
    v = z.w * ga3 + be3; y.w += (v > 0.f ? v : p * v);
    *(float4*)(g_y + o) = y;
    uint2 u;
    u.x = packbf(y.x, y.y);
    u.y = packbf(y.z, y.w);
    *(uint2*)(g_yh + (size_t)nb * 128 + wq * 2) = u;
}

// ---------------------------------------------------------------------------
// 6a) FINAL iter partial: gnapply + residual + xI + masked max over l-chunk
// ---------------------------------------------------------------------------
__global__ void pmax_kernel(const int* __restrict__ posE,
                            const float* __restrict__ gamma,
                            const float* __restrict__ beta,
                            const float* __restrict__ pp)
{
    int b = blockIdx.x, ch = blockIdx.y, w = threadIdx.x;
    int p0 = posE[b * 2] + 1;
    int p1 = posE[b * 2 + 1] + 1;
    float2 st = g_stats[b * G_ + (w >> 6)];
    float ga = gamma[w] * st.y;
    float be = beta[w] - st.x * ga;
    float p = pp[0];
    float m1 = FNEG, m2 = FNEG, m3 = FNEG;
    int l0 = ch * 64;
    int l1 = l0 + 64 < Lp_ ? l0 + 64 : Lp_;
    const float* zp = g_z  + (size_t)(b * Lp_ + l0) * W_ + w;
    const float* yp = g_y  + (size_t)(b * Lp_ + l0) * W_ + w;
    const float* xp = g_xI + (size_t)(b * Lp_ + l0) * W_ + w;
    #pragma unroll 4
    for (int l = l0; l < l1; l++) {
        size_t o = (size_t)(l - l0) * W_;
        float z = zp[o], y = yp[o], xi = xp[o];
        float v = z * ga + be;
        v = v > 0.f ? v : p * v;
        float s = y + v + xi;
        float a1 = s + ((l >= p0) ? NEGF : 0.f);
        float a2 = s + ((l < p0 || l >= p1) ? NEGF : 0.f);
        float a3 = s + ((l < p1) ? NEGF : 0.f);
        m1 = fmaxf(m1, a1);
        m2 = fmaxf(m2, a2);
        m3 = fmaxf(m3, a3);
    }
    int base = ((b * NCH + ch) * 3) * W_ + w;
    g_pmax[base] = m1;
    g_pmax[base + W_] = m2;
    g_pmax[base + 2 * W_] = m3;
}

// ---------------------------------------------------------------------------
// 6b) reduce partials -> g_feat
// ---------------------------------------------------------------------------
__global__ void pmax_reduce()
{
    int b = blockIdx.x, w = threadIdx.x;
    float m1 = FNEG, m2 = FNEG, m3 = FNEG;
    #pragma unroll
    for (int ch = 0; ch < NCH; ch++) {
        int base = ((b * NCH + ch) * 3) * W_ + w;
        m1 = fmaxf(m1, g_pmax[base]);
        m2 = fmaxf(m2, g_pmax[base + W_]);
        m3 = fmaxf(m3, g_pmax[base + 2 * W_]);
    }
    g_feat[b * 3 * W_ + 0 * W_ + w] = m1;
    g_feat[b * 3 * W_ + 1 * W_ + w] = m2;
    g_feat[b * 3 * W_ + 2 * W_ + w] = m3;
}

// ---------------------------------------------------------------------------
// 7) dense head + softmax
// ---------------------------------------------------------------------------
__global__ void dense_kernel(
    const float* __restrict__ d0w, const float* __restrict__ d0b,
    const float* __restrict__ d1w, const float* __restrict__ d1b,
    const float* __restrict__ bndg, const float* __restrict__ bndb,
    const float* __restrict__ bndm, const float* __restrict__ bndv,
    const float* __restrict__ pd,
    const float* __restrict__ finw, const float* __restrict__ finb,
    float* __restrict__ out)
{
    __shared__ float sf[3 * W_];
    __shared__ float sh[W_];
    __shared__ float sl[LBL_];
    __shared__ float red[2];
    int b = blockIdx.x, t = threadIdx.x;

    for (int i = t; i < 3 * W_; i += 256) sf[i] = g_feat[b * 3 * W_ + i];
    __syncthreads();

    float acc = d0b[t];
    {
        const float* wr = d0w + t * (3 * W_);
        #pragma unroll 8
        for (int k = 0; k < 3 * W_; k++) acc += sf[k] * wr[k];
    }
    acc = (acc - bndm[t]) * rsqrtf(bndv[t] + EPSF) * bndg[t] + bndb[t];
    { float p = pd[0]; acc = acc > 0.f ? acc : p * acc; }
    sh[t] = acc;
    __syncthreads();

    float a2 = d1b[t];
    {
        const float* wr = d1w + t * W_;
        #pragma unroll 8
        for (int k = 0; k < W_; k++) a2 += sh[k] * wr[k];
    }
    a2 = (a2 - bndm[W_ + t]) * rsqrtf(bndv[W_ + t] + EPSF) * bndg[W_ + t] + bndb[W_ + t];
    { float p = pd[1]; a2 = a2 > 0.f ? a2 : p * a2; }
    __syncthreads();
    sh[t] = a2;
    __syncthreads();

    if (t < LBL_) {
        float a3 = finb[t];
        const float* wr = finw + t * W_;
        #pragma unroll 8
        for (int k = 0; k < W_; k++) a3 += sh[k] * wr[k];
        sl[t] = a3;
    }
    __syncthreads();
    if (t == 0) {
        float mx = FNEG;
        for (int i = 0; i < LBL_; i++) mx = fmaxf(mx, sl[i]);
        float s = 0.f;
        for (int i = 0; i < LBL_; i++) s += expf(sl[i] - mx);
        red[0] = mx;
        red[1] = 1.f / s;
    }
    __syncthreads();
    if (t < LBL_) out[b * LBL_ + t] = expf(sl[t] - red[0]) * red[1];
}

// ---------------------------------------------------------------------------
// launch
// ---------------------------------------------------------------------------
extern "C" void kernel_launch(void* const* d_in, const int* in_sizes, int n_in,
                              void* d_out, int out_size)
{
    const int*   x      = (const int*)d_in[0];
    const int*   posE   = (const int*)d_in[1];
    const float* pe     = (const float*)d_in[2];
    const float* emb    = (const float*)d_in[3];
    const float* c1w    = (const float*)d_in[4];
    const float* c1b    = (const float*)d_in[5];
    const float* bn1g   = (const float*)d_in[6];
    const float* bn1b   = (const float*)d_in[7];
    const float* bn1m   = (const float*)d_in[8];
    const float* bn1v   = (const float*)d_in[9];
    const float* p1w    = (const float*)d_in[10];
    const float* cbw    = (const float*)d_in[11];
    const float* cbb    = (const float*)d_in[12];
    const float* gng    = (const float*)d_in[13];
    const float* gnb    = (const float*)d_in[14];
    const float* cbp    = (const float*)d_in[15];
    const float* d0w    = (const float*)d_in[16];
    const float* d0b    = (const float*)d_in[17];
    const float* d1w    = (const float*)d_in[18];
    const float* d1b    = (const float*)d_in[19];
    const float* bndg   = (const float*)d_in[20];
    const float* bndb   = (const float*)d_in[21];
    const float* bndm   = (const float*)d_in[22];
    const float* bndv   = (const float*)d_in[23];
    const float* pd     = (const float*)d_in[24];
    const float* finw   = (const float*)d_in[25];
    const float* finb   = (const float*)d_in[26];
    float* out = (float*)d_out;

    const int GEMM_SMEM = 61440;
    const int CB2_SMEM  = 24576 + 67584;   // 92160
    cudaFuncSetAttribute(conv1_tc, cudaFuncAttributeMaxDynamicSharedMemorySize, GEMM_SMEM);
    cudaFuncSetAttribute(cb_tc2,   cudaFuncAttributeMaxDynamicSharedMemorySize, CB2_SMEM);

    prep_w1h<<<(W_ * K1PW + 255) / 256, 256>>>(c1w);
    prep_cbwh<<<(CN_ * W_ * 128 + 255) / 256, 256>>>(cbw);
    embed_h<<<(B_ * L_ * HROW + 4096 + 255) / 256, 256>>>(x, pe, emb);

    {
        dim3 grid(W_ / 128, 4, B_);   // (w-tiles, n-tiles, b)
        conv1_tc<<<grid, 256, GEMM_SMEM>>>(c1b, bn1g, bn1b, bn1m, bn1v, p1w);
    }

    for (int i = 0; i < CN_; i++) {
        dim3 gridc(2, 127);           // (w-tiles, tile-groups of 4)
        cb_tc2<<<gridc, 256, CB2_SMEM>>>(i, cbb + i * W_);
        stats_fin<<<2, 256>>>();
        if (i < CN_ - 1) {
            const float* yprev_ptr;
            if (i == 0) cudaGetSymbolAddress((void**)&yprev_ptr, g_xI);
            else        cudaGetSymbolAddress((void**)&yprev_ptr, g_y);
            gnapply_kernel<<<(NB_ * 64 + 255) / 256, 256>>>(
                yprev_ptr, gng + i * W_, gnb + i * W_, cbp + i);
        } else {
            dim3 gp(B_, NCH);
            pmax_kernel<<<gp, W_>>>(posE, gng + i * W_, gnb + i * W_, cbp + i);
            pmax_reduce<<<B_, W_>>>();
        }
    }

    dense_kernel<<<B_, 256>>>(d0w, d0b, d1w, d1b, bndg, bndb, bndm, bndv,
                              pd, finw, finb, out);

    (void)in_sizes; (void)n_in; (void)out_size;
}

// round 9
// speedup vs baseline: 1.0460x; 1.0460x over previous
#include <cuda_runtime.h>
#include <cuda_bf16.h>
#include <cstdint>

// Problem constants
#define B_   128
#define L_   512
#define W_   256
#define CN_  4
#define G_   4
#define Lp_  508            // L - KH + 1
#define NB_  65024          // B_*Lp_ = 508*128 exactly
#define LBL_ 53
#define EPSF 1e-5f
#define NEGF (-100000.0f)
#define FNEG (-3.0e38f)

#define HROW 68             // b32 per l row of h (136 bf16: 130 data + 6 pad)
#define K1PW 352            // b32 k-pairs per conv1 weight row (704 bf16)
#define C1_NIT 22           // 352/16
#define NCH 8               // l-chunks for partial max

// Scratch (static device memory -- no allocations allowed)
__device__ uint32_t g_hb[(size_t)B_ * L_ * HROW + 4096]; // bf16-pair h, [b*L+l][68]
__device__ uint32_t g_w1h[(size_t)W_ * K1PW];            // conv1 w [w][352]
__device__ uint32_t g_cbwh[(size_t)CN_ * W_ * 128];      // cb w, bf16 [i][256][128 b32]
__device__ uint32_t g_yh[(size_t)NB_ * 128];             // y bf16 pairs [nb][128 b32]
__device__ uint32_t g_xIh[(size_t)NB_ * 128];            // xI bf16 pairs [nb][128 b32]
__device__ float    g_z[(size_t)NB_ * W_];               // [nb][w] fp32
__device__ float    g_psum[B_ * G_ * 2];                 // (sum, sumsq) accum
__device__ float2   g_stats[B_ * G_];                    // (mean, rstd)
__device__ float    g_pmax[B_ * NCH * 3 * W_];
__device__ float    g_feat[B_ * 3 * W_];

// ---------------------------------------------------------------------------
// helpers
// ---------------------------------------------------------------------------
__device__ __forceinline__ uint32_t cvta_s(const void* p) {
    return (uint32_t)__cvta_generic_to_shared(p);
}
__device__ __forceinline__ void cp16(uint32_t s, const void* g) {
    asm volatile("cp.async.cg.shared.global [%0],[%1],16;" :: "r"(s), "l"(g));
}
#define CP_COMMIT() asm volatile("cp.async.commit_group;")
#define CP_WAIT2()  asm volatile("cp.async.wait_group 2;")
#define CP_WAIT1()  asm volatile("cp.async.wait_group 1;")
#define CP_WAIT0()  asm volatile("cp.async.wait_group 0;")

__device__ __forceinline__ void ldm4(uint32_t* r, uint32_t addr) {
    asm volatile("ldmatrix.sync.aligned.m8n8.x4.shared.b16 {%0,%1,%2,%3}, [%4];"
        : "=r"(r[0]), "=r"(r[1]), "=r"(r[2]), "=r"(r[3]) : "r"(addr));
}

__device__ __forceinline__ void mma16(float* c, const uint32_t* a,
                                      uint32_t b0, uint32_t b1) {
    asm volatile(
        "mma.sync.aligned.m16n8k16.row.col.f32.bf16.bf16.f32 "
        "{%0,%1,%2,%3}, {%4,%5,%6,%7}, {%8,%9}, {%0,%1,%2,%3};"
        : "+f"(c[0]), "+f"(c[1]), "+f"(c[2]), "+f"(c[3])
        : "r"(a[0]), "r"(a[1]), "r"(a[2]), "r"(a[3]), "r"(b0), "r"(b1));
}

__device__ __forceinline__ uint32_t packbf(float lo, float hi) {
    __nv_bfloat162 t = __floats2bfloat162_rn(lo, hi);
    return *(uint32_t*)&t;
}
__device__ __forceinline__ float bf_lo(uint32_t u) {
    __nv_bfloat162 t = *(__nv_bfloat162*)&u;
    return __bfloat162float(t.x);
}
__device__ __forceinline__ float bf_hi(uint32_t u) {
    __nv_bfloat162 t = *(__nv_bfloat162*)&u;
    return __bfloat162float(t.y);
}

// ---------------------------------------------------------------------------
// 0a) conv1 weight prep: [w][650] fp32 -> [w][352] bf16-pair (window layout)
// ---------------------------------------------------------------------------
__global__ void prep_w1h(const float* __restrict__ w)
{
    int idx = blockIdx.x * 256 + threadIdx.x;
    if (idx >= W_ * K1PW) return;
    int m = idx / K1PW, kp = idx - m * K1PW;
    int ks = 2 * kp;
    float v0 = 0.f, v1 = 0.f;
    int seg0 = ks / 136, off0 = ks - seg0 * 136;
    if (seg0 < 5 && off0 < 130)     v0 = w[m * 650 + seg0 * 130 + off0];
    int ks1 = ks + 1;
    int seg1 = ks1 / 136, off1 = ks1 - seg1 * 136;
    if (seg1 < 5 && off1 < 130)     v1 = w[m * 650 + seg1 * 130 + off1];
    g_w1h[idx] = packbf(v0, v1);
}

// ---------------------------------------------------------------------------
// 0b) cb weight prep + psum zero init
// ---------------------------------------------------------------------------
__global__ void prep_cbwh(const float* __restrict__ w)
{
    int idx = blockIdx.x * 256 + threadIdx.x;
    if (idx < B_ * G_ * 2) g_psum[idx] = 0.f;
    if (idx >= CN_ * W_ * 128) return;
    int row = idx >> 7;
    int kp  = idx & 127;
    const float* src = w + (size_t)row * W_ + 2 * kp;
    g_cbwh[idx] = packbf(src[0], src[1]);
}

// ---------------------------------------------------------------------------
// 1) embedding + position -> g_hb bf16 pairs [b*L+l][68]; zeros pad + tail
// ---------------------------------------------------------------------------
__global__ void embed_h(const int* __restrict__ x,
                        const float* __restrict__ pe,
                        const float* __restrict__ emb)
{
    int id = blockIdx.x * 256 + threadIdx.x;
    const int MAIN = B_ * L_ * HROW;
    if (id >= MAIN + 4096) return;
    if (id >= MAIN) { g_hb[id] = 0u; return; }
    int bl = id / HROW, t = id - bl * HROW;
    float v0 = 0.f, v1 = 0.f;
    if (t < 64) {
        int tok = x[bl];
        const float* e = emb + (size_t)tok * 128 + 2 * t;
        v0 = e[0]; v1 = e[1];
    } else if (t == 64) {
        v0 = pe[bl * 2]; v1 = pe[bl * 2 + 1];
    }
    g_hb[id] = packbf(v0, v1);
}

// ---------------------------------------------------------------------------
// 2) conv1: C[n][w] = window(h)[n][704] @ w1[w][704]^T, per-batch.
//    Epilogue writes bf16 g_yh and g_xIh only.
// ---------------------------------------------------------------------------
__global__ __launch_bounds__(256, 2) void conv1_tc(
    const float* __restrict__ bias,
    const float* __restrict__ bg, const float* __restrict__ bb,
    const float* __restrict__ bmu, const float* __restrict__ bvv,
    const float* __restrict__ pw)
{
    extern __shared__ uint32_t sm[];
    uint32_t sb = cvta_s(sm);
    int b  = blockIdx.z;
    int m0 = blockIdx.y * 128;     // n-position tile
    int n0 = blockIdx.x * 128;     // w tile
    int t = threadIdx.x, lane = t & 31, wid = t >> 5;
    int wm = wid >> 2, wn = wid & 3;
    int fr = lane >> 2, fc = lane & 3;

    float acc[4][4][4];
    #pragma unroll
    for (int i = 0; i < 4; i++)
        #pragma unroll
        for (int j = 0; j < 4; j++)
            #pragma unroll
            for (int q = 0; q < 4; q++) acc[i][j][q] = 0.f;

    int lr = t >> 1, lc = (t & 1) * 8;
    const uint32_t* agp = g_hb + (size_t)(b * 512 + m0 + lr) * HROW + lc;
    const uint32_t* wgp = g_w1h + (size_t)(n0 + lr) * K1PW + lc;
    uint32_t aS = sb + lr * 80 + lc * 4;
    uint32_t wS = sb + 30720 + lr * 80 + lc * 4;

    uint32_t aAddr[4];
    #pragma unroll
    for (int i = 0; i < 4; i++) {
        int row = wm * 64 + 16 * i + (lane & 15);
        int col = (lane & 16) ? 4 : 0;
        aAddr[i] = sb + row * 80 + col * 4;
    }
    uint32_t bAddr = sb + 30720 + (wn * 32 + lane) * 80;

    #define C1_ISSUE(it_) do { \
        uint32_t so_ = ((it_) % 3) * 10240; \
        cp16(aS + so_, agp + (it_) * 16); \
        cp16(aS + so_ + 16, agp + (it_) * 16 + 4); \
        cp16(wS + so_, wgp + (it_) * 16); \
        cp16(wS + so_ + 16, wgp + (it_) * 16 + 4); \
    } while (0)

    C1_ISSUE(0); CP_COMMIT();
    C1_ISSUE(1); CP_COMMIT();

    for (int it = 0; it < C1_NIT; it++) {
        if (it < C1_NIT - 1) CP_WAIT1(); else CP_WAIT0();
        __syncthreads();
        uint32_t so = (it % 3) * 10240;
        #pragma unroll
        for (int ss = 0; ss < 2; ss++) {
            uint32_t ko = so + ss * 32;
            uint32_t af[4][4], b0q[4], b1q[4];
            #pragma unroll
            for (int i = 0; i < 4; i++) ldm4(af[i], aAddr[i] + ko);
            ldm4(b0q, bAddr + ko);
            ldm4(b1q, bAddr + ko + 16);
            #pragma unroll
            for (int i = 0; i < 4; i++)
                #pragma unroll
                for (int j = 0; j < 4; j++)
                    mma16(acc[i][j], af[i], b0q[j], b1q[j]);
        }
        if (it + 2 < C1_NIT) { C1_ISSUE(it + 2); CP_COMMIT(); }
    }

    float p = pw[0];
    #pragma unroll
    for (int j = 0; j < 4; j++) {
        int c = n0 + wn * 32 + 8 * j + 2 * fc;
        float s0 = rsqrtf(bvv[c] + EPSF) * bg[c];
        float o0 = bb[c] - bmu[c] * s0 + bias[c] * s0;
        float s1 = rsqrtf(bvv[c + 1] + EPSF) * bg[c + 1];
        float o1 = bb[c + 1] - bmu[c + 1] * s1 + bias[c + 1] * s1;
        #pragma unroll
        for (int i = 0; i < 4; i++) {
            int r0 = m0 + wm * 64 + 16 * i + fr;
            int r1 = r0 + 8;
            if (r0 < Lp_) {
                size_t nb = (size_t)b * Lp_ + r0;
                float v0 = acc[i][j][0] * s0 + o0;
                float v1 = acc[i][j][1] * s1 + o1;
                v0 = v0 > 0.f ? v0 : p * v0;
                v1 = v1 > 0.f ? v1 : p * v1;
                uint32_t pk = packbf(v0, v1);
                g_yh[nb * 128 + (c >> 1)]  = pk;
                g_xIh[nb * 128 + (c >> 1)] = pk;
            }
            if (r1 < Lp_) {
                size_t nb = (size_t)b * Lp_ + r1;
                float v2 = acc[i][j][2] * s0 + o0;
                float v3 = acc[i][j][3] * s1 + o1;
                v2 = v2 > 0.f ? v2 : p * v2;
                v3 = v3 > 0.f ? v3 : p * v3;
                uint32_t pk = packbf(v2, v3);
                g_yh[nb * 128 + (c >> 1)]  = pk;
                g_xIh[nb * 128 + (c >> 1)] = pk;
            }
        }
    }
}

// ---------------------------------------------------------------------------
// 3) cb GEMM: weight-resident multi-tile (R8 design).
// ---------------------------------------------------------------------------
__global__ __launch_bounds__(256, 2) void cb_tc2(int blk, const float* __restrict__ bias)
{
    extern __shared__ uint32_t sm4[];
    __shared__ float sred[8];
    uint32_t sb = cvta_s(sm4);
    const uint32_t A0 = sb;                 // 4 stages * 6144 B
    const uint32_t W0 = sb + 24576;         // 128 rows * 528 B
    int n0 = blockIdx.x * 128;
    int tgrp = blockIdx.y;                  // 0..126, tiles tgrp*4 .. +3
    int t = threadIdx.x, lane = t & 31, wid = t >> 5;
    int wm = wid >> 2, wn = wid & 3;
    int fr = lane >> 2, fc = lane & 3;
    if (t < 8) sred[t] = 0.f;

    {
        const char* wbase = (const char*)g_cbwh + (size_t)(blk * 256 + n0) * 512;
        #pragma unroll
        for (int i = 0; i < 16; i++) {
            int c = t + 256 * i;
            int row = c >> 5, col = c & 31;
            cp16(W0 + row * 528 + col * 16, wbase + row * 512 + col * 16);
        }
    }

    int arow = t >> 1, ahalf = t & 1;
    const char* abase = (const char*)g_yh +
        ((size_t)(tgrp * 4) * 128 + arow) * 512 + ahalf * 16;
    uint32_t aS = A0 + arow * 48 + ahalf * 16;

    #define CB2_ISSUE(s_) \
        cp16(aS + ((s_) & 3) * 6144, \
             abase + (size_t)((s_) >> 4) * 65536 + ((s_) & 15) * 32)

    CB2_ISSUE(0); CP_COMMIT();
    CB2_ISSUE(1); CP_COMMIT();
    CB2_ISSUE(2); CP_COMMIT();

    uint32_t aAddr[4];
    #pragma unroll
    for (int i = 0; i < 4; i++)
        aAddr[i] = A0 + (wm * 64 + 16 * i + (lane & 15)) * 48 + ((lane & 16) ? 16 : 0);
    uint32_t bAddr = W0 + (wn * 32 + lane) * 528;

    float acc[4][4][4];

    for (int s = 0; s < 64; s++) {
        if ((s & 15) == 0) {
            #pragma unroll
            for (int i = 0; i < 4; i++)
                #pragma unroll
                for (int j = 0; j < 4; j++)
                    #pragma unroll
                    for (int q = 0; q < 4; q++) acc[i][j][q] = 0.f;
        }
        if (s < 62) CP_WAIT2(); else if (s == 62) CP_WAIT1(); else CP_WAIT0();
        __syncthreads();
        {
            uint32_t so = (s & 3) * 6144;
            uint32_t ko = (s & 15) * 32;
            uint32_t af[4][4], b0q[4], b1q[4];
            #pragma unroll
            for (int i = 0; i < 4; i++) ldm4(af[i], aAddr[i] + so);
            ldm4(b0q, bAddr + ko);
            ldm4(b1q, bAddr + ko + 16);
            #pragma unroll
            for (int i = 0; i < 4; i++)
                #pragma unroll
                for (int j = 0; j < 4; j++)
                    mma16(acc[i][j], af[i], b0q[j], b1q[j]);
        }
        if (s + 3 < 64) { CB2_ISSUE(s + 3); CP_COMMIT(); }

        if ((s & 15) == 15) {
            int tile = tgrp * 4 + (s >> 4);
            int m0 = tile * 128;
            float rs[4][2], rq[4][2];
            #pragma unroll
            for (int i = 0; i < 4; i++) { rs[i][0] = rs[i][1] = rq[i][0] = rq[i][1] = 0.f; }
            #pragma unroll
            for (int j = 0; j < 4; j++) {
                int c = n0 + wn * 32 + 8 * j + 2 * fc;
                float bi0 = bias[c], bi1 = bias[c + 1];
                #pragma unroll
                for (int i = 0; i < 4; i++) {
                    size_t r0 = m0 + wm * 64 + 16 * i + fr;
                    size_t r1 = r0 + 8;
                    float v0 = acc[i][j][0] + bi0, v1 = acc[i][j][1] + bi1;
                    float v2 = acc[i][j][2] + bi0, v3 = acc[i][j][3] + bi1;
                    *(float2*)(g_z + r0 * W_ + c) = make_float2(v0, v1);
                    *(float2*)(g_z + r1 * W_ + c) = make_float2(v2, v3);
                    rs[i][0] += v0 + v1; rq[i][0] += v0 * v0 + v1 * v1;
                    rs[i][1] += v2 + v3; rq[i][1] += v2 * v2 + v3 * v3;
                }
            }
            int b0v = m0 / Lp_;
            int thr = (b0v + 1) * Lp_;
            float s0 = 0.f, q0 = 0.f, s1 = 0.f, q1 = 0.f;
            #pragma unroll
            for (int i = 0; i < 4; i++) {
                int r0 = m0 + wm * 64 + 16 * i + fr;
                if (r0 >= thr) { s1 += rs[i][0]; q1 += rq[i][0]; }
                else           { s0 += rs[i][0]; q0 += rq[i][0]; }
                if (r0 + 8 >= thr) { s1 += rs[i][1]; q1 += rq[i][1]; }
                else               { s0 += rs[i][1]; q0 += rq[i][1]; }
            }
            #pragma unroll
            for (int o = 16; o > 0; o >>= 1) {
                s0 += __shfl_xor_sync(0xffffffffu, s0, o);
                q0 += __shfl_xor_sync(0xffffffffu, q0, o);
                s1 += __shfl_xor_sync(0xffffffffu, s1, o);
                q1 += __shfl_xor_sync(0xffffffffu, q1, o);
            }
            int gslot = wn >> 1;
            if (lane == 0) {
                atomicAdd(&sred[gslot * 2 + 0], s0);
                atomicAdd(&sred[gslot * 2 + 1], q0);
                atomicAdd(&sred[4 + gslot * 2 + 0], s1);
                atomicAdd(&sred[4 + gslot * 2 + 1], q1);
            }
            __syncthreads();
            if (t < 8) {
                int bslot = t >> 2, gs = (t >> 1) & 1, sq = t & 1;
                int bb = b0v + bslot;
                if (bb < B_) {
                    int g = (n0 >> 6) + gs;
                    atomicAdd(&g_psum[(bb * G_ + g) * 2 + sq], sred[t]);
                }
                sred[t] = 0.f;
            }
            __syncthreads();
        }
    }
}

// ---------------------------------------------------------------------------
// 4) stats finalize: psum -> g_stats; re-zero psum for next iteration
// ---------------------------------------------------------------------------
__global__ void stats_fin()
{
    int t = blockIdx.x * 256 + threadIdx.x;
    if (t >= B_ * G_) return;
    float s = g_psum[t * 2], q = g_psum[t * 2 + 1];
    float cnt = (float)(64 * Lp_);
    float mean = s / cnt;
    float var  = q / cnt - mean * mean;
    g_stats[t] = make_float2(mean, rsqrtf(var + EPSF));
    g_psum[t * 2] = 0.f;
    g_psum[t * 2 + 1] = 0.f;
}

// ---------------------------------------------------------------------------
// 5) GroupNorm apply + PReLU + residual, bf16 y-chain:
//    yh = bf16( unpack(yh) + prelu(norm(z)) )
// ---------------------------------------------------------------------------
__global__ void gnapply_kernel(const float* __restrict__ gamma,
                               const float* __restrict__ beta,
                               const float* __restrict__ pp)
{
    unsigned idx = blockIdx.x * 256u + threadIdx.x;
    if (idx >= (unsigned)NB_ * 128u) return;
    unsigned nb = idx >> 7, wp = idx & 127;
    unsigned w0 = wp * 2;
    unsigned b = nb / Lp_;
    float2 st = g_stats[b * G_ + (w0 >> 6)];
    float ga0 = gamma[w0] * st.y,     be0 = beta[w0] - st.x * ga0;
    float ga1 = gamma[w0 + 1] * st.y, be1 = beta[w0 + 1] - st.x * ga1;
    float p = pp[0];
    float2 z = *(const float2*)(g_z + (size_t)nb * W_ + w0);
    uint32_t yu = g_yh[(size_t)nb * 128 + wp];
    float v0 = z.x * ga0 + be0; v0 = v0 > 0.f ? v0 : p * v0;
    float v1 = z.y * ga1 + be1; v1 = v1 > 0.f ? v1 : p * v1;
    float y0 = bf_lo(yu) + v0;
    float y1 = bf_hi(yu) + v1;
    g_yh[(size_t)nb * 128 + wp] = packbf(y0, y1);
}

// ---------------------------------------------------------------------------
// 6a) FINAL iter partial: gnapply + residual + xI + masked max over l-chunk
// ---------------------------------------------------------------------------
__global__ void pmax_kernel(const int* __restrict__ posE,
                            const float* __restrict__ gamma,
                            const float* __restrict__ beta,
                            const float* __restrict__ pp)
{
    int b = blockIdx.x, ch = blockIdx.y, w = threadIdx.x;
    int p0 = posE[b * 2] + 1;
    int p1 = posE[b * 2 + 1] + 1;
    float2 st = g_stats[b * G_ + (w >> 6)];
    float ga = gamma[w] * st.y;
    float be = beta[w] - st.x * ga;
    float p = pp[0];
    int half = w & 1;
    float m1 = FNEG, m2 = FNEG, m3 = FNEG;
    int l0 = ch * 64;
    int l1 = l0 + 64 < Lp_ ? l0 + 64 : Lp_;
    const float*    zp = g_z   + (size_t)(b * Lp_ + l0) * W_ + w;
    const uint32_t* yp = g_yh  + (size_t)(b * Lp_ + l0) * 128 + (w >> 1);
    const uint32_t* xp = g_xIh + (size_t)(b * Lp_ + l0) * 128 + (w >> 1);
    #pragma unroll 4
    for (int l = l0; l < l1; l++) {
        int d = l - l0;
        float z = zp[(size_t)d * W_];
        uint32_t yu = yp[(size_t)d * 128];
        uint32_t xu = xp[(size_t)d * 128];
        float y  = half ? bf_hi(yu) : bf_lo(yu);
        float xi = half ? bf_hi(xu) : bf_lo(xu);
        float v = z * ga + be;
        v = v > 0.f ? v : p * v;
        float s = y + v + xi;
        float a1 = s + ((l >= p0) ? NEGF : 0.f);
        float a2 = s + ((l < p0 || l >= p1) ? NEGF : 0.f);
        float a3 = s + ((l < p1) ? NEGF : 0.f);
        m1 = fmaxf(m1, a1);
        m2 = fmaxf(m2, a2);
        m3 = fmaxf(m3, a3);
    }
    int base = ((b * NCH + ch) * 3) * W_ + w;
    g_pmax[base] = m1;
    g_pmax[base + W_] = m2;
    g_pmax[base + 2 * W_] = m3;
}

// ---------------------------------------------------------------------------
// 6b) reduce partials -> g_feat
// ---------------------------------------------------------------------------
__global__ void pmax_reduce()
{
    int b = blockIdx.x, w = threadIdx.x;
    float m1 = FNEG, m2 = FNEG, m3 = FNEG;
    #pragma unroll
    for (int ch = 0; ch < NCH; ch++) {
        int base = ((b * NCH + ch) * 3) * W_ + w;
        m1 = fmaxf(m1, g_pmax[base]);
        m2 = fmaxf(m2, g_pmax[base + W_]);
        m3 = fmaxf(m3, g_pmax[base + 2 * W_]);
    }
    g_feat[b * 3 * W_ + 0 * W_ + w] = m1;
    g_feat[b * 3 * W_ + 1 * W_ + w] = m2;
    g_feat[b * 3 * W_ + 2 * W_ + w] = m3;
}

// ---------------------------------------------------------------------------
// 7) dense head + softmax
// ---------------------------------------------------------------------------
__global__ void dense_kernel(
    const float* __restrict__ d0w, const float* __restrict__ d0b,
    const float* __restrict__ d1w, const float* __restrict__ d1b,
    const float* __restrict__ bndg, const float* __restrict__ bndb,
    const float* __restrict__ bndm, const float* __restrict__ bndv,
    const float* __restrict__ pd,
    const float* __restrict__ finw, const float* __restrict__ finb,
    float* __restrict__ out)
{
    __shared__ float sf[3 * W_];
    __shared__ float sh[W_];
    __shared__ float sl[LBL_];
    __shared__ float red[2];
    int b = blockIdx.x, t = threadIdx.x;

    for (int i = t; i < 3 * W_; i += 256) sf[i] = g_feat[b * 3 * W_ + i];
    __syncthreads();

    float acc = d0b[t];
    {
        const float* wr = d0w + t * (3 * W_);
        #pragma unroll 8
        for (int k = 0; k < 3 * W_; k++) acc += sf[k] * wr[k];
    }
    acc = (acc - bndm[t]) * rsqrtf(bndv[t] + EPSF) * bndg[t] + bndb[t];
    { float p = pd[0]; acc = acc > 0.f ? acc : p * acc; }
    sh[t] = acc;
    __syncthreads();

    float a2 = d1b[t];
    {
        const float* wr = d1w + t * W_;
        #pragma unroll 8
        for (int k = 0; k < W_; k++) a2 += sh[k] * wr[k];
    }
    a2 = (a2 - bndm[W_ + t]) * rsqrtf(bndv[W_ + t] + EPSF) * bndg[W_ + t] + bndb[W_ + t];
    { float p = pd[1]; a2 = a2 > 0.f ? a2 : p * a2; }
    __syncthreads();
    sh[t] = a2;
    __syncthreads();

    if (t < LBL_) {
        float a3 = finb[t];
        const float* wr = finw + t * W_;
        #pragma unroll 8
        for (int k = 0; k < W_; k++) a3 += sh[k] * wr[k];
        sl[t] = a3;
    }
    __syncthreads();
    if (t == 0) {
        float mx = FNEG;
        for (int i = 0; i < LBL_; i++) mx = fmaxf(mx, sl[i]);
        float s = 0.f;
        for (int i = 0; i < LBL_; i++) s += expf(sl[i] - mx);
        red[0] = mx;
        red[1] = 1.f / s;
    }
    __syncthreads();
    if (t < LBL_) out[b * LBL_ + t] = expf(sl[t] - red[0]) * red[1];
}

// ---------------------------------------------------------------------------
// launch
// ---------------------------------------------------------------------------
extern "C" void kernel_launch(void* const* d_in, const int* in_sizes, int n_in,
                              void* d_out, int out_size)
{
    const int*   x      = (const int*)d_in[0];
    const int*   posE   = (const int*)d_in[1];
    const float* pe     = (const float*)d_in[2];
    const float* emb    = (const float*)d_in[3];
    const float* c1w    = (const float*)d_in[4];
    const float* c1b    = (const float*)d_in[5];
    const float* bn1g   = (const float*)d_in[6];
    const float* bn1b   = (const float*)d_in[7];
    const float* bn1m   = (const float*)d_in[8];
    const float* bn1v   = (const float*)d_in[9];
    const float* p1w    = (const float*)d_in[10];
    const float* cbw    = (const float*)d_in[11];
    const float* cbb    = (const float*)d_in[12];
    const float* gng    = (const float*)d_in[13];
    const float* gnb    = (const float*)d_in[14];
    const float* cbp    = (const float*)d_in[15];
    const float* d0w    = (const float*)d_in[16];
    const float* d0b    = (const float*)d_in[17];
    const float* d1w    = (const float*)d_in[18];
    const float* d1b    = (const float*)d_in[19];
    const float* bndg   = (const float*)d_in[20];
    const float* bndb   = (const float*)d_in[21];
    const float* bndm   = (const float*)d_in[22];
    const float* bndv   = (const float*)d_in[23];
    const float* pd     = (const float*)d_in[24];
    const float* finw   = (const float*)d_in[25];
    const float* finb   = (const float*)d_in[26];
    float* out = (float*)d_out;

    const int GEMM_SMEM = 61440;
    const int CB2_SMEM  = 24576 + 67584;   // 92160
    cudaFuncSetAttribute(conv1_tc, cudaFuncAttributeMaxDynamicSharedMemorySize, GEMM_SMEM);
    cudaFuncSetAttribute(cb_tc2,   cudaFuncAttributeMaxDynamicSharedMemorySize, CB2_SMEM);

    prep_w1h<<<(W_ * K1PW + 255) / 256, 256>>>(c1w);
    prep_cbwh<<<(CN_ * W_ * 128 + 255) / 256, 256>>>(cbw);
    embed_h<<<(B_ * L_ * HROW + 4096 + 255) / 256, 256>>>(x, pe, emb);

    {
        dim3 grid(W_ / 128, 4, B_);   // (w-tiles, n-tiles, b)
        conv1_tc<<<grid, 256, GEMM_SMEM>>>(c1b, bn1g, bn1b, bn1m, bn1v, p1w);
    }

    for (int i = 0; i < CN_; i++) {
        dim3 gridc(2, 127);           // (w-tiles, tile-groups of 4)
        cb_tc2<<<gridc, 256, CB2_SMEM>>>(i, cbb + i * W_);
        stats_fin<<<2, 256>>>();
        if (i < CN_ - 1) {
            gnapply_kernel<<<(NB_ * 128 + 255) / 256, 256>>>(
                gng + i * W_, gnb + i * W_, cbp + i);
        } else {
            dim3 gp(B_, NCH);
            pmax_kernel<<<gp, W_>>>(posE, gng + i * W_, gnb + i * W_, cbp + i);
            pmax_reduce<<<B_, W_>>>();
        }
    }

    dense_kernel<<<B_, 256>>>(d0w, d0b, d1w, d1b, bndg, bndb, bndm, bndv,
                              pd, finw, finb, out);

    (void)in_sizes; (void)n_in; (void)out_size;
}

// round 10
// speedup vs baseline: 1.0708x; 1.0236x over previous
#include <cuda_runtime.h>
#include <cuda_bf16.h>
#include <cstdint>

// Problem constants
#define B_   128
#define L_   512
#define W_   256
#define CN_  4
#define G_   4
#define Lp_  508            // L - KH + 1
#define NB_  65024          // B_*Lp_ = 508*128 exactly
#define LBL_ 53
#define EPSF 1e-5f
#define NEGF (-100000.0f)
#define FNEG (-3.0e38f)
#define GCNT 32512.0f       // 64 * Lp_

#define HROW 68             // b32 per l row of h (136 bf16: 130 data + 6 pad)
#define K1PW 352            // b32 k-pairs per conv1 weight row (704 bf16)
#define C1_NIT 22           // 352/16
#define NCH 8               // l-chunks for partial max

// Scratch (static device memory -- no allocations allowed)
__device__ uint32_t g_hb[(size_t)B_ * L_ * HROW + 4096]; // bf16-pair h, [b*L+l][68]
__device__ uint32_t g_w1h[(size_t)W_ * K1PW];            // conv1 w [w][352]
__device__ uint32_t g_cbwh[(size_t)CN_ * W_ * 128];      // cb w, bf16 [i][256][128 b32]
__device__ uint32_t g_yh[(size_t)NB_ * 128];             // y bf16 pairs [nb][128 b32]
__device__ uint32_t g_xIh[(size_t)NB_ * 128];            // xI bf16 pairs [nb][128 b32]
__device__ uint32_t g_zh[(size_t)NB_ * 128];             // z bf16 pairs [nb][128 b32]
__device__ float    g_psum2[CN_ * B_ * G_ * 2];          // per-layer (sum, sumsq)
__device__ float    g_pmax[B_ * NCH * 3 * W_];

// ---------------------------------------------------------------------------
// helpers
// ---------------------------------------------------------------------------
__device__ __forceinline__ uint32_t cvta_s(const void* p) {
    return (uint32_t)__cvta_generic_to_shared(p);
}
__device__ __forceinline__ void cp16(uint32_t s, const void* g) {
    asm volatile("cp.async.cg.shared.global [%0],[%1],16;" :: "r"(s), "l"(g));
}
#define CP_COMMIT() asm volatile("cp.async.commit_group;")
#define CP_WAIT2()  asm volatile("cp.async.wait_group 2;")
#define CP_WAIT1()  asm volatile("cp.async.wait_group 1;")
#define CP_WAIT0()  asm volatile("cp.async.wait_group 0;")

__device__ __forceinline__ void ldm4(uint32_t* r, uint32_t addr) {
    asm volatile("ldmatrix.sync.aligned.m8n8.x4.shared.b16 {%0,%1,%2,%3}, [%4];"
        : "=r"(r[0]), "=r"(r[1]), "=r"(r[2]), "=r"(r[3]) : "r"(addr));
}

__device__ __forceinline__ void mma16(float* c, const uint32_t* a,
                                      uint32_t b0, uint32_t b1) {
    asm volatile(
        "mma.sync.aligned.m16n8k16.row.col.f32.bf16.bf16.f32 "
        "{%0,%1,%2,%3}, {%4,%5,%6,%7}, {%8,%9}, {%0,%1,%2,%3};"
        : "+f"(c[0]), "+f"(c[1]), "+f"(c[2]), "+f"(c[3])
        : "r"(a[0]), "r"(a[1]), "r"(a[2]), "r"(a[3]), "r"(b0), "r"(b1));
}

__device__ __forceinline__ uint32_t packbf(float lo, float hi) {
    __nv_bfloat162 t = __floats2bfloat162_rn(lo, hi);
    return *(uint32_t*)&t;
}
__device__ __forceinline__ float bf_lo(uint32_t u) {
    __nv_bfloat162 t = *(__nv_bfloat162*)&u;
    return __bfloat162float(t.x);
}
__device__ __forceinline__ float bf_hi(uint32_t u) {
    __nv_bfloat162 t = *(__nv_bfloat162*)&u;
    return __bfloat162float(t.y);
}
__device__ __forceinline__ float2 gn_stats(int blk, int b, int g) {
    const float* ps = g_psum2 + ((blk * B_ + b) * G_ + g) * 2;
    float s = __ldg(ps), q = __ldg(ps + 1);
    float mean = s / GCNT;
    float var  = q / GCNT - mean * mean;
    return make_float2(mean, rsqrtf(var + EPSF));
}

// ---------------------------------------------------------------------------
// 0a) conv1 weight prep: [w][650] fp32 -> [w][352] bf16-pair (window layout)
// ---------------------------------------------------------------------------
__global__ void prep_w1h(const float* __restrict__ w)
{
    int idx = blockIdx.x * 256 + threadIdx.x;
    if (idx >= W_ * K1PW) return;
    int m = idx / K1PW, kp = idx - m * K1PW;
    int ks = 2 * kp;
    float v0 = 0.f, v1 = 0.f;
    int seg0 = ks / 136, off0 = ks - seg0 * 136;
    if (seg0 < 5 && off0 < 130)     v0 = w[m * 650 + seg0 * 130 + off0];
    int ks1 = ks + 1;
    int seg1 = ks1 / 136, off1 = ks1 - seg1 * 136;
    if (seg1 < 5 && off1 < 130)     v1 = w[m * 650 + seg1 * 130 + off1];
    g_w1h[idx] = packbf(v0, v1);
}

// ---------------------------------------------------------------------------
// 0b) cb weight prep + per-layer psum zero init (once)
// ---------------------------------------------------------------------------
__global__ void prep_cbwh(const float* __restrict__ w)
{
    int idx = blockIdx.x * 256 + threadIdx.x;
    if (idx < CN_ * B_ * G_ * 2) g_psum2[idx] = 0.f;
    if (idx >= CN_ * W_ * 128) return;
    int row = idx >> 7;
    int kp  = idx & 127;
    const float* src = w + (size_t)row * W_ + 2 * kp;
    g_cbwh[idx] = packbf(src[0], src[1]);
}

// ---------------------------------------------------------------------------
// 1) embedding + position -> g_hb bf16 pairs [b*L+l][68]; zeros pad + tail
// ---------------------------------------------------------------------------
__global__ void embed_h(const int* __restrict__ x,
                        const float* __restrict__ pe,
                        const float* __restrict__ emb)
{
    int id = blockIdx.x * 256 + threadIdx.x;
    const int MAIN = B_ * L_ * HROW;
    if (id >= MAIN + 4096) return;
    if (id >= MAIN) { g_hb[id] = 0u; return; }
    int bl = id / HROW, t = id - bl * HROW;
    float v0 = 0.f, v1 = 0.f;
    if (t < 64) {
        int tok = x[bl];
        const float* e = emb + (size_t)tok * 128 + 2 * t;
        v0 = e[0]; v1 = e[1];
    } else if (t == 64) {
        v0 = pe[bl * 2]; v1 = pe[bl * 2 + 1];
    }
    g_hb[id] = packbf(v0, v1);
}

// ---------------------------------------------------------------------------
// 2) conv1: C[n][w] = window(h)[n][704] @ w1[w][704]^T, per-batch.
//    Epilogue writes bf16 g_yh and g_xIh only.
// ---------------------------------------------------------------------------
__global__ __launch_bounds__(256, 2) void conv1_tc(
    const float* __restrict__ bias,
    const float* __restrict__ bg, const float* __restrict__ bb,
    const float* __restrict__ bmu, const float* __restrict__ bvv,
    const float* __restrict__ pw)
{
    extern __shared__ uint32_t sm[];
    uint32_t sb = cvta_s(sm);
    int b  = blockIdx.z;
    int m0 = blockIdx.y * 128;     // n-position tile
    int n0 = blockIdx.x * 128;     // w tile
    int t = threadIdx.x, lane = t & 31, wid = t >> 5;
    int wm = wid >> 2, wn = wid & 3;
    int fr = lane >> 2, fc = lane & 3;

    float acc[4][4][4];
    #pragma unroll
    for (int i = 0; i < 4; i++)
        #pragma unroll
        for (int j = 0; j < 4; j++)
            #pragma unroll
            for (int q = 0; q < 4; q++) acc[i][j][q] = 0.f;

    int lr = t >> 1, lc = (t & 1) * 8;
    const uint32_t* agp = g_hb + (size_t)(b * 512 + m0 + lr) * HROW + lc;
    const uint32_t* wgp = g_w1h + (size_t)(n0 + lr) * K1PW + lc;
    uint32_t aS = sb + lr * 80 + lc * 4;
    uint32_t wS = sb + 30720 + lr * 80 + lc * 4;

    uint32_t aAddr[4];
    #pragma unroll
    for (int i = 0; i < 4; i++) {
        int row = wm * 64 + 16 * i + (lane & 15);
        int col = (lane & 16) ? 4 : 0;
        aAddr[i] = sb + row * 80 + col * 4;
    }
    uint32_t bAddr = sb + 30720 + (wn * 32 + lane) * 80;

    #define C1_ISSUE(it_) do { \
        uint32_t so_ = ((it_) % 3) * 10240; \
        cp16(aS + so_, agp + (it_) * 16); \
        cp16(aS + so_ + 16, agp + (it_) * 16 + 4); \
        cp16(wS + so_, wgp + (it_) * 16); \
        cp16(wS + so_ + 16, wgp + (it_) * 16 + 4); \
    } while (0)

    C1_ISSUE(0); CP_COMMIT();
    C1_ISSUE(1); CP_COMMIT();

    for (int it = 0; it < C1_NIT; it++) {
        if (it < C1_NIT - 1) CP_WAIT1(); else CP_WAIT0();
        __syncthreads();
        uint32_t so = (it % 3) * 10240;
        #pragma unroll
        for (int ss = 0; ss < 2; ss++) {
            uint32_t ko = so + ss * 32;
            uint32_t af[4][4], b0q[4], b1q[4];
            #pragma unroll
            for (int i = 0; i < 4; i++) ldm4(af[i], aAddr[i] + ko);
            ldm4(b0q, bAddr + ko);
            ldm4(b1q, bAddr + ko + 16);
            #pragma unroll
            for (int i = 0; i < 4; i++)
                #pragma unroll
                for (int j = 0; j < 4; j++)
                    mma16(acc[i][j], af[i], b0q[j], b1q[j]);
        }
        if (it + 2 < C1_NIT) { C1_ISSUE(it + 2); CP_COMMIT(); }
    }

    float p = pw[0];
    #pragma unroll
    for (int j = 0; j < 4; j++) {
        int c = n0 + wn * 32 + 8 * j + 2 * fc;
        float s0 = rsqrtf(bvv[c] + EPSF) * bg[c];
        float o0 = bb[c] - bmu[c] * s0 + bias[c] * s0;
        float s1 = rsqrtf(bvv[c + 1] + EPSF) * bg[c + 1];
        float o1 = bb[c + 1] - bmu[c + 1] * s1 + bias[c + 1] * s1;
        #pragma unroll
        for (int i = 0; i < 4; i++) {
            int r0 = m0 + wm * 64 + 16 * i + fr;
            int r1 = r0 + 8;
            if (r0 < Lp_) {
                size_t nb = (size_t)b * Lp_ + r0;
                float v0 = acc[i][j][0] * s0 + o0;
                float v1 = acc[i][j][1] * s1 + o1;
                v0 = v0 > 0.f ? v0 : p * v0;
                v1 = v1 > 0.f ? v1 : p * v1;
                uint32_t pk = packbf(v0, v1);
                g_yh[nb * 128 + (c >> 1)]  = pk;
                g_xIh[nb * 128 + (c >> 1)] = pk;
            }
            if (r1 < Lp_) {
                size_t nb = (size_t)b * Lp_ + r1;
                float v2 = acc[i][j][2] * s0 + o0;
                float v3 = acc[i][j][3] * s1 + o1;
                v2 = v2 > 0.f ? v2 : p * v2;
                v3 = v3 > 0.f ? v3 : p * v3;
                uint32_t pk = packbf(v2, v3);
                g_yh[nb * 128 + (c >> 1)]  = pk;
                g_xIh[nb * 128 + (c >> 1)] = pk;
            }
        }
    }
}

// ---------------------------------------------------------------------------
// 3) cb GEMM: weight-resident multi-tile; z stored bf16, stats fp32 fused.
// ---------------------------------------------------------------------------
__global__ __launch_bounds__(256, 2) void cb_tc2(int blk, const float* __restrict__ bias)
{
    extern __shared__ uint32_t sm4[];
    __shared__ float sred[8];
    uint32_t sb = cvta_s(sm4);
    const uint32_t A0 = sb;                 // 4 stages * 6144 B
    const uint32_t W0 = sb + 24576;         // 128 rows * 528 B
    int n0 = blockIdx.x * 128;
    int tgrp = blockIdx.y;                  // 0..126, tiles tgrp*4 .. +3
    int t = threadIdx.x, lane = t & 31, wid = t >> 5;
    int wm = wid >> 2, wn = wid & 3;
    int fr = lane >> 2, fc = lane & 3;
    if (t < 8) sred[t] = 0.f;

    {
        const char* wbase = (const char*)g_cbwh + (size_t)(blk * 256 + n0) * 512;
        #pragma unroll
        for (int i = 0; i < 16; i++) {
            int c = t + 256 * i;
            int row = c >> 5, col = c & 31;
            cp16(W0 + row * 528 + col * 16, wbase + row * 512 + col * 16);
        }
    }

    int arow = t >> 1, ahalf = t & 1;
    const char* abase = (const char*)g_yh +
        ((size_t)(tgrp * 4) * 128 + arow) * 512 + ahalf * 16;
    uint32_t aS = A0 + arow * 48 + ahalf * 16;

    #define CB2_ISSUE(s_) \
        cp16(aS + ((s_) & 3) * 6144, \
             abase + (size_t)((s_) >> 4) * 65536 + ((s_) & 15) * 32)

    CB2_ISSUE(0); CP_COMMIT();
    CB2_ISSUE(1); CP_COMMIT();
    CB2_ISSUE(2); CP_COMMIT();

    uint32_t aAddr[4];
    #pragma unroll
    for (int i = 0; i < 4; i++)
        aAddr[i] = A0 + (wm * 64 + 16 * i + (lane & 15)) * 48 + ((lane & 16) ? 16 : 0);
    uint32_t bAddr = W0 + (wn * 32 + lane) * 528;

    float acc[4][4][4];
    float* psl = g_psum2 + blk * B_ * G_ * 2;

    for (int s = 0; s < 64; s++) {
        if ((s & 15) == 0) {
            #pragma unroll
            for (int i = 0; i < 4; i++)
                #pragma unroll
                for (int j = 0; j < 4; j++)
                    #pragma unroll
                    for (int q = 0; q < 4; q++) acc[i][j][q] = 0.f;
        }
        if (s < 62) CP_WAIT2(); else if (s == 62) CP_WAIT1(); else CP_WAIT0();
        __syncthreads();
        {
            uint32_t so = (s & 3) * 6144;
            uint32_t ko = (s & 15) * 32;
            uint32_t af[4][4], b0q[4], b1q[4];
            #pragma unroll
            for (int i = 0; i < 4; i++) ldm4(af[i], aAddr[i] + so);
            ldm4(b0q, bAddr + ko);
            ldm4(b1q, bAddr + ko + 16);
            #pragma unroll
            for (int i = 0; i < 4; i++)
                #pragma unroll
                for (int j = 0; j < 4; j++)
                    mma16(acc[i][j], af[i], b0q[j], b1q[j]);
        }
        if (s + 3 < 64) { CB2_ISSUE(s + 3); CP_COMMIT(); }

        if ((s & 15) == 15) {
            int tile = tgrp * 4 + (s >> 4);
            int m0 = tile * 128;
            float rs[4][2], rq[4][2];
            #pragma unroll
            for (int i = 0; i < 4; i++) { rs[i][0] = rs[i][1] = rq[i][0] = rq[i][1] = 0.f; }
            #pragma unroll
            for (int j = 0; j < 4; j++) {
                int c = n0 + wn * 32 + 8 * j + 2 * fc;
                int cp = c >> 1;
                float bi0 = bias[c], bi1 = bias[c + 1];
                #pragma unroll
                for (int i = 0; i < 4; i++) {
                    size_t r0 = m0 + wm * 64 + 16 * i + fr;
                    size_t r1 = r0 + 8;
                    float v0 = acc[i][j][0] + bi0, v1 = acc[i][j][1] + bi1;
                    float v2 = acc[i][j][2] + bi0, v3 = acc[i][j][3] + bi1;
                    g_zh[r0 * 128 + cp] = packbf(v0, v1);
                    g_zh[r1 * 128 + cp] = packbf(v2, v3);
                    rs[i][0] += v0 + v1; rq[i][0] += v0 * v0 + v1 * v1;
                    rs[i][1] += v2 + v3; rq[i][1] += v2 * v2 + v3 * v3;
                }
            }
            int b0v = m0 / Lp_;
            int thr = (b0v + 1) * Lp_;
            float s0 = 0.f, q0 = 0.f, s1 = 0.f, q1 = 0.f;
            #pragma unroll
            for (int i = 0; i < 4; i++) {
                int r0 = m0 + wm * 64 + 16 * i + fr;
                if (r0 >= thr) { s1 += rs[i][0]; q1 += rq[i][0]; }
                else           { s0 += rs[i][0]; q0 += rq[i][0]; }
                if (r0 + 8 >= thr) { s1 += rs[i][1]; q1 += rq[i][1]; }
                else               { s0 += rs[i][1]; q0 += rq[i][1]; }
            }
            #pragma unroll
            for (int o = 16; o > 0; o >>= 1) {
                s0 += __shfl_xor_sync(0xffffffffu, s0, o);
                q0 += __shfl_xor_sync(0xffffffffu, q0, o);
                s1 += __shfl_xor_sync(0xffffffffu, s1, o);
                q1 += __shfl_xor_sync(0xffffffffu, q1, o);
            }
            int gslot = wn >> 1;
            if (lane == 0) {
                atomicAdd(&sred[gslot * 2 + 0], s0);
                atomicAdd(&sred[gslot * 2 + 1], q0);
                atomicAdd(&sred[4 + gslot * 2 + 0], s1);
                atomicAdd(&sred[4 + gslot * 2 + 1], q1);
            }
            __syncthreads();
            if (t < 8) {
                int bslot = t >> 2, gs = (t >> 1) & 1, sq = t & 1;
                int bb = b0v + bslot;
                if (bb < B_) {
                    int g = (n0 >> 6) + gs;
                    atomicAdd(&psl[(bb * G_ + g) * 2 + sq], sred[t]);
                }
                sred[t] = 0.f;
            }
            __syncthreads();
        }
    }
}

// ---------------------------------------------------------------------------
// 5) GroupNorm apply + PReLU + residual, bf16 y-chain; inline stats
// ---------------------------------------------------------------------------
__global__ void gnapply_kernel(int blk,
                               const float* __restrict__ gamma,
                               const float* __restrict__ beta,
                               const float* __restrict__ pp)
{
    unsigned idx = blockIdx.x * 256u + threadIdx.x;
    if (idx >= (unsigned)NB_ * 128u) return;
    unsigned nb = idx >> 7, wp = idx & 127;
    unsigned w0 = wp * 2;
    unsigned b = nb / Lp_;
    float2 st = gn_stats(blk, b, w0 >> 6);
    float ga0 = gamma[w0] * st.y,     be0 = beta[w0] - st.x * ga0;
    float ga1 = gamma[w0 + 1] * st.y, be1 = beta[w0 + 1] - st.x * ga1;
    float p = pp[0];
    uint32_t zu = g_zh[(size_t)nb * 128 + wp];
    uint32_t yu = g_yh[(size_t)nb * 128 + wp];
    float v0 = bf_lo(zu) * ga0 + be0; v0 = v0 > 0.f ? v0 : p * v0;
    float v1 = bf_hi(zu) * ga1 + be1; v1 = v1 > 0.f ? v1 : p * v1;
    float y0 = bf_lo(yu) + v0;
    float y1 = bf_hi(yu) + v1;
    g_yh[(size_t)nb * 128 + wp] = packbf(y0, y1);
}

// ---------------------------------------------------------------------------
// 6a) FINAL iter partial: gnapply + residual + xI + masked max over l-chunk
// ---------------------------------------------------------------------------
__global__ void pmax_kernel(int blk,
                            const int* __restrict__ posE,
                            const float* __restrict__ gamma,
                            const float* __restrict__ beta,
                            const float* __restrict__ pp)
{
    int b = blockIdx.x, ch = blockIdx.y, w = threadIdx.x;
    int p0 = posE[b * 2] + 1;
    int p1 = posE[b * 2 + 1] + 1;
    float2 st = gn_stats(blk, b, w >> 6);
    float ga = gamma[w] * st.y;
    float be = beta[w] - st.x * ga;
    float p = pp[0];
    int half = w & 1;
    float m1 = FNEG, m2 = FNEG, m3 = FNEG;
    int l0 = ch * 64;
    int l1 = l0 + 64 < Lp_ ? l0 + 64 : Lp_;
    const uint32_t* zp = g_zh  + (size_t)(b * Lp_ + l0) * 128 + (w >> 1);
    const uint32_t* yp = g_yh  + (size_t)(b * Lp_ + l0) * 128 + (w >> 1);
    const uint32_t* xp = g_xIh + (size_t)(b * Lp_ + l0) * 128 + (w >> 1);
    #pragma unroll 4
    for (int l = l0; l < l1; l++) {
        size_t d = (size_t)(l - l0) * 128;
        uint32_t zu = zp[d];
        uint32_t yu = yp[d];
        uint32_t xu = xp[d];
        float z  = half ? bf_hi(zu) : bf_lo(zu);
        float y  = half ? bf_hi(yu) : bf_lo(yu);
        float xi = half ? bf_hi(xu) : bf_lo(xu);
        float v = z * ga + be;
        v = v > 0.f ? v : p * v;
        float s = y + v + xi;
        float a1 = s + ((l >= p0) ? NEGF : 0.f);
        float a2 = s + ((l < p0 || l >= p1) ? NEGF : 0.f);
        float a3 = s + ((l < p1) ? NEGF : 0.f);
        m1 = fmaxf(m1, a1);
        m2 = fmaxf(m2, a2);
        m3 = fmaxf(m3, a3);
    }
    int base = ((b * NCH + ch) * 3) * W_ + w;
    g_pmax[base] = m1;
    g_pmax[base + W_] = m2;
    g_pmax[base + 2 * W_] = m3;
}

// ---------------------------------------------------------------------------
// 7) dense head + softmax; fused pmax reduction preamble
// ---------------------------------------------------------------------------
__global__ void dense_kernel(
    const float* __restrict__ d0w, const float* __restrict__ d0b,
    const float* __restrict__ d1w, const float* __restrict__ d1b,
    const float* __restrict__ bndg, const float* __restrict__ bndb,
    const float* __restrict__ bndm, const float* __restrict__ bndv,
    const float* __restrict__ pd,
    const float* __restrict__ finw, const float* __restrict__ finb,
    float* __restrict__ out)
{
    __shared__ float sf[3 * W_];
    __shared__ float sh[W_];
    __shared__ float sl[LBL_];
    __shared__ float red[2];
    int b = blockIdx.x, t = threadIdx.x;

    // fused pmax reduce: thread t = channel w
    {
        float m1 = FNEG, m2 = FNEG, m3 = FNEG;
        #pragma unroll
        for (int ch = 0; ch < NCH; ch++) {
            int base = ((b * NCH + ch) * 3) * W_ + t;
            m1 = fmaxf(m1, g_pmax[base]);
            m2 = fmaxf(m2, g_pmax[base + W_]);
            m3 = fmaxf(m3, g_pmax[base + 2 * W_]);
        }
        sf[t] = m1;
        sf[W_ + t] = m2;
        sf[2 * W_ + t] = m3;
    }
    __syncthreads();

    float acc = d0b[t];
    {
        const float* wr = d0w + t * (3 * W_);
        #pragma unroll 8
        for (int k = 0; k < 3 * W_; k++) acc += sf[k] * wr[k];
    }
    acc = (acc - bndm[t]) * rsqrtf(bndv[t] + EPSF) * bndg[t] + bndb[t];
    { float p = pd[0]; acc = acc > 0.f ? acc : p * acc; }
    sh[t] = acc;
    __syncthreads();

    float a2 = d1b[t];
    {
        const float* wr = d1w + t * W_;
        #pragma unroll 8
        for (int k = 0; k < W_; k++) a2 += sh[k] * wr[k];
    }
    a2 = (a2 - bndm[W_ + t]) * rsqrtf(bndv[W_ + t] + EPSF) * bndg[W_ + t] + bndb[W_ + t];
    { float p = pd[1]; a2 = a2 > 0.f ? a2 : p * a2; }
    __syncthreads();
    sh[t] = a2;
    __syncthreads();

    if (t < LBL_) {
        float a3 = finb[t];
        const float* wr = finw + t * W_;
        #pragma unroll 8
        for (int k = 0; k < W_; k++) a3 += sh[k] * wr[k];
        sl[t] = a3;
    }
    __syncthreads();
    if (t == 0) {
        float mx = FNEG;
        for (int i = 0; i < LBL_; i++) mx = fmaxf(mx, sl[i]);
        float s = 0.f;
        for (int i = 0; i < LBL_; i++) s += expf(sl[i] - mx);
        red[0] = mx;
        red[1] = 1.f / s;
    }
    __syncthreads();
    if (t < LBL_) out[b * LBL_ + t] = expf(sl[t] - red[0]) * red[1];
}

// ---------------------------------------------------------------------------
// launch
// ---------------------------------------------------------------------------
extern "C" void kernel_launch(void* const* d_in, const int* in_sizes, int n_in,
                              void* d_out, int out_size)
{
    const int*   x      = (const int*)d_in[0];
    const int*   posE   = (const int*)d_in[1];
    const float* pe     = (const float*)d_in[2];
    const float* emb    = (const float*)d_in[3];
    const float* c1w    = (const float*)d_in[4];
    const float* c1b    = (const float*)d_in[5];
    const float* bn1g   = (const float*)d_in[6];
    const float* bn1b   = (const float*)d_in[7];
    const float* bn1m   = (const float*)d_in[8];
    const float* bn1v   = (const float*)d_in[9];
    const float* p1w    = (const float*)d_in[10];
    const float* cbw    = (const float*)d_in[11];
    const float* cbb    = (const float*)d_in[12];
    const float* gng    = (const float*)d_in[13];
    const float* gnb    = (const float*)d_in[14];
    const float* cbp    = (const float*)d_in[15];
    const float* d0w    = (const float*)d_in[16];
    const float* d0b    = (const float*)d_in[17];
    const float* d1w    = (const float*)d_in[18];
    const float* d1b    = (const float*)d_in[19];
    const float* bndg   = (const float*)d_in[20];
    const float* bndb   = (const float*)d_in[21];
    const float* bndm   = (const float*)d_in[22];
    const float* bndv   = (const float*)d_in[23];
    const float* pd     = (const float*)d_in[24];
    const float* finw   = (const float*)d_in[25];
    const float* finb   = (const float*)d_in[26];
    float* out = (float*)d_out;

    const int GEMM_SMEM = 61440;
    const int CB2_SMEM  = 24576 + 67584;   // 92160
    cudaFuncSetAttribute(conv1_tc, cudaFuncAttributeMaxDynamicSharedMemorySize, GEMM_SMEM);
    cudaFuncSetAttribute(cb_tc2,   cudaFuncAttributeMaxDynamicSharedMemorySize, CB2_SMEM);

    prep_w1h<<<(W_ * K1PW + 255) / 256, 256>>>(c1w);
    prep_cbwh<<<(CN_ * W_ * 128 + 255) / 256, 256>>>(cbw);
    embed_h<<<(B_ * L_ * HROW + 4096 + 255) / 256, 256>>>(x, pe, emb);

    {
        dim3 grid(W_ / 128, 4, B_);   // (w-tiles, n-tiles, b)
        conv1_tc<<<grid, 256, GEMM_SMEM>>>(c1b, bn1g, bn1b, bn1m, bn1v, p1w);
    }

    for (int i = 0; i < CN_; i++) {
        dim3 gridc(2, 127);           // (w-tiles, tile-groups of 4)
        cb_tc2<<<gridc, 256, CB2_SMEM>>>(i, cbb + i * W_);
        if (i < CN_ - 1) {
            gnapply_kernel<<<(NB_ * 128 + 255) / 256, 256>>>(
                i, gng + i * W_, gnb + i * W_, cbp + i);
        } else {
            dim3 gp(B_, NCH);
            pmax_kernel<<<gp, W_>>>(i, posE, gng + i * W_, gnb + i * W_, cbp + i);
        }
    }

    dense_kernel<<<B_, 256>>>(d0w, d0b, d1w, d1b, bndg, bndb, bndm, bndv,
                              pd, finw, finb, out);

    (void)in_sizes; (void)n_in; (void)out_size;
}